// round 12
// baseline (speedup 1.0000x reference)
#include <cuda_runtime.h>
#include <math.h>

#define TT   512
#define OUTD 500
#define NTHR 352

typedef unsigned long long ull;

// ---------------- packed f32x2 helpers (FFMA2) ----------------
__device__ __forceinline__ ull pack2(float lo, float hi) {
    ull u;
    asm("mov.b64 %0,{%1,%2};" : "=l"(u) : "f"(lo), "f"(hi));
    return u;
}
__device__ __forceinline__ ull ffma2(ull a, ull b, ull c) {
    ull d;
    asm("fma.rn.f32x2 %0,%1,%2,%3;" : "=l"(d) : "l"(a), "l"(b), "l"(c));
    return d;
}
__device__ __forceinline__ float red2(ull u) {
    float lo, hi;
    asm("mov.b64 {%0,%1},%2;" : "=f"(lo), "=f"(hi) : "l"(u));
    return lo + hi;
}

// 2-accumulator dot: weights in registers, vector in shared (LDS.64)
template <int NP>
__device__ __forceinline__ float dot_rw(const ull* __restrict__ w,
                                        const ull* __restrict__ v) {
    ull a0 = 0ull, a1 = 0ull;
#pragma unroll
    for (int p = 0; p < NP; p += 2) {
        a0 = ffma2(w[p], v[p], a0);
        if (p + 1 < NP) a1 = ffma2(w[p + 1], v[p + 1], a1);
    }
    return red2(a0) + red2(a1);
}
// 4-accumulator dot for the long K=100 reductions
template <int NP>
__device__ __forceinline__ float dot_rw4(const ull* __restrict__ w,
                                         const ull* __restrict__ v) {
    ull a0 = 0ull, a1 = 0ull, a2 = 0ull, a3 = 0ull;
#pragma unroll
    for (int p = 0; p < NP; p += 4) {
        a0 = ffma2(w[p], v[p], a0);
        if (p + 1 < NP) a1 = ffma2(w[p + 1], v[p + 1], a1);
        if (p + 2 < NP) a2 = ffma2(w[p + 2], v[p + 2], a2);
        if (p + 3 < NP) a3 = ffma2(w[p + 3], v[p + 3], a3);
    }
    return (red2(a0) + red2(a1)) + (red2(a2) + red2(a3));
}

// ---------------- fast activations (MUFU-based) ----------------
__device__ __forceinline__ float sigm(float x) {
    return __fdividef(1.0f, 1.0f + __expf(-x));
}
__device__ __forceinline__ float tanh_f(float x) {
    x = fminf(fmaxf(x, -15.0f), 15.0f);
    float e = __expf(2.0f * x);
    return __fdividef(e - 1.0f, e + 1.0f);
}
__device__ __forceinline__ float softplus_f(float x) {
    return fmaxf(x, 0.0f) + __logf(1.0f + __expf(-fabsf(x)));
}

__global__ void __launch_bounds__(NTHR, 1)
arfssm_kernel(const float* __restrict__ x, const float* __restrict__ eps,
              const float* __restrict__ W_ih1, const float* __restrict__ W_hh1,
              const float* __restrict__ b_ih1, const float* __restrict__ b_hh1,
              const float* __restrict__ W_ih2, const float* __restrict__ W_hh2,
              const float* __restrict__ b_ih2, const float* __restrict__ b_hh2,
              const float* __restrict__ dzW1, const float* __restrict__ dzb1,
              const float* __restrict__ dzWloc, const float* __restrict__ dzbloc,
              const float* __restrict__ dzWsc, const float* __restrict__ dzbsc,
              const float* __restrict__ dxW1, const float* __restrict__ dxb1,
              const float* __restrict__ dxWloc, const float* __restrict__ dxbloc,
              const float* __restrict__ dxWsc, const float* __restrict__ dxbsc,
              const float* __restrict__ h1_0, const float* __restrict__ h2_0,
              float* __restrict__ out) {
    __shared__ __align__(16) float s_z[2][104];        // [b][100] (pad 104)
    __shared__ __align__(16) float s_hdz[2][20];       // [b]
    __shared__ __align__(16) float s_hdx[2][2][20];    // [parity][b]
    __shared__ __align__(16) float s_h2[2][2][12];     // [parity][b]  (h2 with 1-step delay)
    __shared__ __align__(16) float s_x[3][2][104];     // triple buffer [t%3][b][100]
    __shared__ float s_dzW1p[20 * 11];                 // dzW1 rows padded to 11 (coprime 32)
    __shared__ float s_dxW1p[20 * 21];                 // dxW1 rows padded to 21 (coprime 32)

    const int tid  = threadIdx.x;
    const int lane = tid & 31;
    const int wid  = tid >> 5;
    const int b0   = blockIdx.x * 2;

    // ---- cooperative preload of x slots 0,1 ----
    for (int i = tid; i < 100; i += NTHR) {
        int s = i / 50, r = i % 50, bb = r / 25, f = r % 25;
        ((float4*)&s_x[s][bb][0])[f] =
            ((const float4*)(x + ((size_t)(b0 + bb) * TT + s) * 100))[f];
    }
    // padded small matrices into shared
    for (int i = tid; i < 220; i += NTHR) {
        int row = i / 11, k = i % 11;
        s_dzW1p[i] = (k < 10) ? dzW1[row * 10 + k] : 0.0f;
    }
    for (int i = tid; i < 420; i += NTHR) {
        int row = i / 21, k = i % 21;
        s_dxW1p[i] = (k < 20) ? dxW1[row * 20 + k] : 0.0f;
    }

    // ---------------- per-role register state ----------------
    // heads (tid 0..199)
    ull wzl[10], wzs[10], wxl[10], wxs[10];
    float bzl = 0.f, bzs = 0.f, bxl = 0.f, bxs = 0.f;
    float erA = 0.f, erB = 0.f;            // eps for even / odd steps, prefetched t+2
    int hb = 0, hj = 0;
    // recurrence warps (wid 7,8)
    ull wa[50];                            // FULL K=100 W_ih1 row (register-resident)
    float whh1r[10];
    float bih1r = 0.f, bhh1r = 0.f, dzb1r = 0.f, dxb1r = 0.f;
    float h1p = 0.f, gh1own = 0.f;
    // RNN2 warps (wid 9,10)
    ull wih2r[50];                         // FULL K=100 W_ih2 row
    float whh2r[10], h2all[10];
    float bih2r = 0.f, bhh2r = 0.f, h2own = 0.f;
    int rb = 0;
#pragma unroll
    for (int q = 0; q < 50; q++) { wa[q] = 0ull; wih2r[q] = 0ull; }
#pragma unroll
    for (int k = 0; k < 10; k++) { whh1r[k] = whh2r[k] = h2all[k] = 0.f; }

    if (tid < 200) {
        hb = tid / 100; hj = tid % 100;
        const float2* p;
        p = (const float2*)(dzWloc + hj * 20);
#pragma unroll
        for (int q = 0; q < 10; q++) { float2 v = p[q]; wzl[q] = pack2(v.x, v.y); }
        p = (const float2*)(dzWsc + hj * 20);
#pragma unroll
        for (int q = 0; q < 10; q++) { float2 v = p[q]; wzs[q] = pack2(v.x, v.y); }
        p = (const float2*)(dxWloc + hj * 20);
#pragma unroll
        for (int q = 0; q < 10; q++) { float2 v = p[q]; wxl[q] = pack2(v.x, v.y); }
        p = (const float2*)(dxWsc + hj * 20);
#pragma unroll
        for (int q = 0; q < 10; q++) { float2 v = p[q]; wxs[q] = pack2(v.x, v.y); }
        bzl = dzbloc[hj]; bzs = dzbsc[hj]; bxl = dxbloc[hj]; bxs = dxbsc[hj];
        erA = eps[((size_t)(b0 + hb) * TT + 0) * 100 + hj];
        erB = eps[((size_t)(b0 + hb) * TT + 1) * 100 + hj];
    } else if (wid == 7 || wid == 8) {
        rb = wid - 7;
        if (lane < 30) {
            const float2* p = (const float2*)(W_ih1 + lane * 100);
#pragma unroll
            for (int q = 0; q < 50; q++) { float2 v = p[q]; wa[q] = pack2(v.x, v.y); }
#pragma unroll
            for (int k = 0; k < 10; k++) whh1r[k] = W_hh1[lane * 10 + k];
            bih1r = b_ih1[lane]; bhh1r = b_hh1[lane];
            float a = bhh1r;
#pragma unroll
            for (int k = 0; k < 10; k++) a = fmaf(whh1r[k], h1_0[k], a);
            gh1own = a;                      // gh1 for t=0
        }
        if (lane < 20) {
            dzb1r = dzb1[lane]; dxb1r = dxb1[lane];
            float a = dzb1r;
#pragma unroll
            for (int k = 0; k < 10; k++) a = fmaf(dzW1[lane * 10 + k], h1_0[k], a);
            s_hdz[rb][lane] = fmaxf(a, 0.0f);    // hdz for t=0
        }
        if (lane < 10) h1p = h1_0[lane];
    } else if (wid >= 9) {
        rb = wid - 9;
        if (lane < 30) {
            const float2* p = (const float2*)(W_ih2 + lane * 100);
#pragma unroll
            for (int q = 0; q < 50; q++) { float2 v = p[q]; wih2r[q] = pack2(v.x, v.y); }
#pragma unroll
            for (int k = 0; k < 10; k++) whh2r[k] = W_hh2[lane * 10 + k];
            bih2r = b_ih2[lane]; bhh2r = b_hh2[lane];
        }
#pragma unroll
        for (int k = 0; k < 10; k++) h2all[k] = h2_0[k];
        if (lane < 10) {
            h2own = h2_0[lane];
            s_h2[0][rb][lane] = h2own;           // h2_shift for t=0
        }
    }
    __syncthreads();

    float4 pre = make_float4(0.f, 0.f, 0.f, 0.f);
    float ghA = 0.f, ghB = 0.f, hdx2 = 0.f;

    for (int t = 0; t < TT; t++) {
        const int cur = t & 1, nxt = cur ^ 1;

        // ================= S1 =================
        if (tid < 200) {                        // z-head
            const ull* hz = (const ull*)&s_hdz[hb][0];
            float er_use = (t & 1) ? erB : erA;
            float zl = dot_rw<10>(wzl, hz) + bzl;
            float zs = softplus_f(dot_rw<10>(wzs, hz) + bzs);
            float zt = fmaf(zs, er_use, zl);
            s_z[hb][hj] = zt;
            float* o = out + ((size_t)(b0 + hb) * TT + t) * OUTD;
            o[200 + hj] = zl; o[300 + hj] = zs; o[400 + hj] = zt;
            if (t + 2 < TT) {                   // depth-2 eps prefetch (t+2)
                float v = eps[((size_t)(b0 + hb) * TT + t + 2) * 100 + hj];
                if (t & 1) erB = v; else erA = v;
            }
        } else if (wid == 7 || wid == 8) {      // REC: pre-gather for S2
            ghA = __shfl_sync(0xFFFFFFFFu, gh1own, lane + 10);
            ghB = __shfl_sync(0xFFFFFFFFu, gh1own, lane + 20);
            float c = dxb1r;
            if (lane < 20) {
#pragma unroll
                for (int k = 0; k < 10; k++)
                    c = fmaf(s_dxW1p[lane * 21 + 10 + k], s_h2[cur][rb][k], c);
            }
            hdx2 = c;
        } else if (wid >= 9) {                  // x(t+2) prefetch issue
            if (lane < 25 && t + 2 < TT)
                pre = ((const float4*)(x + ((size_t)(b0 + rb) * TT + t + 2) * 100))[lane];
        }
        __syncthreads();

        // ================= S2 =================
        if (tid < 200) {                        // x-head for t-1 (pipelined)
            if (t > 0) {
                const ull* hv = (const ull*)&s_hdx[nxt][hb][0];
                float xl = dot_rw<10>(wxl, hv) + bxl;
                float xs = softplus_f(dot_rw<10>(wxs, hv) + bxs);
                float* o = out + ((size_t)(b0 + hb) * TT + (t - 1)) * OUTD;
                o[hj] = xl; o[100 + hj] = xs;
            }
        } else if (wid == 7 || wid == 8) {      // REC: gi1 -> GRU1 -> fanout
            const ull* zr = (const ull*)&s_z[rb][0];
            float g = dot_rw4<50>(wa, zr) + bih1r;
            float gA = __shfl_sync(0xFFFFFFFFu, g, lane + 10);
            float gB = __shfl_sync(0xFFFFFFFFu, g, lane + 20);
            float r  = sigm(g + gh1own);
            float uu = sigm(gA + ghA);
            float n  = tanh_f(fmaf(r, ghB, gB));
            float h1n = fmaf(uu, h1p - n, n);
            h1p = h1n;
            float hk[10];
#pragma unroll
            for (int k = 0; k < 10; k++) hk[k] = __shfl_sync(0xFFFFFFFFu, h1n, k);
            if (lane < 20) {
                float a = dzb1r;
#pragma unroll
                for (int k = 0; k < 10; k++) a = fmaf(s_dzW1p[lane * 11 + k], hk[k], a);
                s_hdz[rb][lane] = fmaxf(a, 0.0f);
                float c = hdx2;
#pragma unroll
                for (int k = 0; k < 10; k++) c = fmaf(s_dxW1p[lane * 21 + k], hk[k], c);
                s_hdx[cur][rb][lane] = fmaxf(c, 0.0f);
            }
            float a2 = bhh1r;                   // gh1 for t+1
#pragma unroll
            for (int k = 0; k < 10; k++) a2 = fmaf(whh1r[k], hk[k], a2);
            gh1own = a2;
        } else if (wid >= 9) {                  // RNN2 (fully async) + prefetch stash
            const ull* xr = (const ull*)&s_x[t % 3][rb][0];
            float g = dot_rw4<50>(wih2r, xr) + bih2r;
            float gA = __shfl_sync(0xFFFFFFFFu, g, lane + 10);
            float gB = __shfl_sync(0xFFFFFFFFu, g, lane + 20);
            float gh = bhh2r;
#pragma unroll
            for (int k = 0; k < 10; k++) gh = fmaf(whh2r[k], h2all[k], gh);
            float ghA2 = __shfl_sync(0xFFFFFFFFu, gh, lane + 10);
            float ghB2 = __shfl_sync(0xFFFFFFFFu, gh, lane + 20);
            float r  = sigm(g + gh);
            float uu = sigm(gA + ghA2);
            float n  = tanh_f(fmaf(r, ghB2, gB));
            float h2n = fmaf(uu, h2own - n, n);
            if (lane < 10) h2own = h2n;
#pragma unroll
            for (int k = 0; k < 10; k++) h2all[k] = __shfl_sync(0xFFFFFFFFu, h2n, k);
            if (lane < 10) s_h2[nxt][rb][lane] = h2n;   // published for step t+1
            if (lane < 25 && t + 2 < TT)
                ((float4*)&s_x[(t + 2) % 3][rb][0])[lane] = pre;
        }
        __syncthreads();
    }

    // ---- epilogue: x outputs for t = TT-1 ----
    if (tid < 200) {
        const int p = (TT - 1) & 1;
        const ull* hv = (const ull*)&s_hdx[p][hb][0];
        float xl = dot_rw<10>(wxl, hv) + bxl;
        float xs = softplus_f(dot_rw<10>(wxs, hv) + bxs);
        float* o = out + ((size_t)(b0 + hb) * TT + (TT - 1)) * OUTD;
        o[hj] = xl; o[100 + hj] = xs;
    }
}

extern "C" void kernel_launch(void* const* d_in, const int* in_sizes, int n_in,
                              void* d_out, int out_size) {
    const float* x      = (const float*)d_in[0];
    const float* eps    = (const float*)d_in[1];
    const float* W_ih1  = (const float*)d_in[2];
    const float* W_hh1  = (const float*)d_in[3];
    const float* b_ih1  = (const float*)d_in[4];
    const float* b_hh1  = (const float*)d_in[5];
    const float* W_ih2  = (const float*)d_in[6];
    const float* W_hh2  = (const float*)d_in[7];
    const float* b_ih2  = (const float*)d_in[8];
    const float* b_hh2  = (const float*)d_in[9];
    const float* dzW1   = (const float*)d_in[10];
    const float* dzb1   = (const float*)d_in[11];
    const float* dzWloc = (const float*)d_in[12];
    const float* dzbloc = (const float*)d_in[13];
    const float* dzWsc  = (const float*)d_in[14];
    const float* dzbsc  = (const float*)d_in[15];
    const float* dxW1   = (const float*)d_in[16];
    const float* dxb1   = (const float*)d_in[17];
    const float* dxWloc = (const float*)d_in[18];
    const float* dxbloc = (const float*)d_in[19];
    const float* dxWsc  = (const float*)d_in[20];
    const float* dxbsc  = (const float*)d_in[21];
    const float* h1_0   = (const float*)d_in[22];
    const float* h2_0   = (const float*)d_in[23];

    int Btot = in_sizes[0] / (TT * 100);   // 256
    int grid = Btot / 2;                   // 128 blocks, 2 batches each

    arfssm_kernel<<<grid, NTHR>>>(x, eps, W_ih1, W_hh1, b_ih1, b_hh1,
                                  W_ih2, W_hh2, b_ih2, b_hh2,
                                  dzW1, dzb1, dzWloc, dzbloc, dzWsc, dzbsc,
                                  dxW1, dxb1, dxWloc, dxbloc, dxWsc, dxbsc,
                                  h1_0, h2_0, (float*)d_out);
}

// round 13
// speedup vs baseline: 3.4548x; 3.4548x over previous
#include <cuda_runtime.h>
#include <math.h>

#define TT   512
#define BBT  256
#define OUTD 500

typedef unsigned long long ull;

// static device scratch (no allocation)
__device__ float g_h1buf[BBT * TT * 10];   // h1 AFTER step t
__device__ float g_h2buf[BBT * TT * 10];   // h2_shift at t (before consuming x_t)

// ---------------- packed f32x2 helpers ----------------
__device__ __forceinline__ ull pack2(float lo, float hi) {
    ull u; asm("mov.b64 %0,{%1,%2};" : "=l"(u) : "f"(lo), "f"(hi)); return u;
}
__device__ __forceinline__ ull ffma2(ull a, ull b, ull c) {
    ull d; asm("fma.rn.f32x2 %0,%1,%2,%3;" : "=l"(d) : "l"(a), "l"(b), "l"(c)); return d;
}
__device__ __forceinline__ float red2(ull u) {
    float lo, hi; asm("mov.b64 {%0,%1},%2;" : "=f"(lo), "=f"(hi) : "l"(u)); return lo + hi;
}
template <int NP>
__device__ __forceinline__ float dot_rw(const ull* __restrict__ w,
                                        const ull* __restrict__ v) {
    ull a0 = 0ull, a1 = 0ull;
#pragma unroll
    for (int p = 0; p < NP; p += 2) {
        a0 = ffma2(w[p], v[p], a0);
        if (p + 1 < NP) a1 = ffma2(w[p + 1], v[p + 1], a1);
    }
    return red2(a0) + red2(a1);
}
template <int NP>
__device__ __forceinline__ float dot4(const ull* __restrict__ w,
                                      const ull* __restrict__ v) {
    ull a0 = 0ull, a1 = 0ull, a2 = 0ull, a3 = 0ull;
#pragma unroll
    for (int p = 0; p < NP; p += 4) {
        a0 = ffma2(w[p], v[p], a0);
        if (p + 1 < NP) a1 = ffma2(w[p + 1], v[p + 1], a1);
        if (p + 2 < NP) a2 = ffma2(w[p + 2], v[p + 2], a2);
        if (p + 3 < NP) a3 = ffma2(w[p + 3], v[p + 3], a3);
    }
    return (red2(a0) + red2(a1)) + (red2(a2) + red2(a3));
}

// ---------------- fast activations ----------------
__device__ __forceinline__ float sigm(float x) {
    return __fdividef(1.0f, 1.0f + __expf(-x));
}
__device__ __forceinline__ float tanh_f(float x) {
    x = fminf(fmaxf(x, -15.0f), 15.0f);
    float e = __expf(2.0f * x);
    return __fdividef(e - 1.0f, e + 1.0f);
}
__device__ __forceinline__ float softplus_f(float x) {
    return fmaxf(x, 0.0f) + __logf(1.0f + __expf(-fabsf(x)));
}

// =====================================================================
// Kernel 1: scans. 128 blocks x 128 threads. No block syncs in loop.
//   warp 0/1: h1 scan for batch b0+0 / b0+1 (z outputs + h1 trajectory)
//   warp 2/3: h2 (RNN2) scan for batch b0+0 / b0+1 (h2_shift trajectory)
// =====================================================================
__global__ void __launch_bounds__(128, 1)
scan_kernel(const float* __restrict__ x, const float* __restrict__ eps,
            const float* __restrict__ W_ih1, const float* __restrict__ W_hh1,
            const float* __restrict__ b_ih1, const float* __restrict__ b_hh1,
            const float* __restrict__ W_ih2, const float* __restrict__ W_hh2,
            const float* __restrict__ b_ih2, const float* __restrict__ b_hh2,
            const float* __restrict__ dzW1, const float* __restrict__ dzb1,
            const float* __restrict__ dzWloc, const float* __restrict__ dzbloc,
            const float* __restrict__ dzWsc, const float* __restrict__ dzbsc,
            const float* __restrict__ h1_0, const float* __restrict__ h2_0,
            float* __restrict__ out) {
    __shared__ ull s_wa[30 * 51];                     // W_ih1 packed pairs, pitch 51
    __shared__ __align__(16) float s_z[2][104];       // z_t per batch
    __shared__ __align__(16) float s_x[3][2][104];    // x triple buffer (RNN2)

    const int tid  = threadIdx.x;
    const int lane = tid & 31;
    const int wid  = tid >> 5;
    const int b0   = blockIdx.x * 2;

    // cooperative: W_ih1 -> shared (packed pairs)
    for (int i = tid; i < 1500; i += 128) {
        int j = i / 50, p = i % 50;
        s_wa[j * 51 + p] = pack2(W_ih1[j * 100 + 2 * p], W_ih1[j * 100 + 2 * p + 1]);
    }
    // x slots 0,1
    for (int i = tid; i < 100; i += 128) {
        int s = i / 50, r = i % 50, bb = r / 25, f = r % 25;
        ((float4*)&s_x[s][bb][0])[f] =
            ((const float4*)(x + ((size_t)(b0 + bb) * TT + s) * 100))[f];
    }

    if (wid < 2) {
        // ================= h1 scan warp =================
        const int bb = b0 + wid;
        const int nr = (lane < 4) ? 4 : 3;             // z rows per lane
        ull wzl[4][10], wzs[4][10];
        float bzl4[4], bzs4[4], er4[4];
        float dzr[10], whh1r[10];
        float bdz = 0.f, bhh1 = 0.f, bih1 = 0.f, h1p = 0.f;
#pragma unroll
        for (int m = 0; m < 4; m++) {
            int row = lane + 32 * m;
            bzl4[m] = bzs4[m] = er4[m] = 0.f;
#pragma unroll
            for (int q = 0; q < 10; q++) { wzl[m][q] = 0ull; wzs[m][q] = 0ull; }
            if (row < 100) {
                const float2* pl = (const float2*)(dzWloc + row * 20);
                const float2* ps = (const float2*)(dzWsc + row * 20);
#pragma unroll
                for (int q = 0; q < 10; q++) {
                    float2 a = pl[q]; wzl[m][q] = pack2(a.x, a.y);
                    float2 b = ps[q]; wzs[m][q] = pack2(b.x, b.y);
                }
                bzl4[m] = dzbloc[row]; bzs4[m] = dzbsc[row];
                er4[m]  = eps[((size_t)bb * TT) * 100 + row];
            }
        }
#pragma unroll
        for (int k = 0; k < 10; k++) { dzr[k] = 0.f; whh1r[k] = 0.f; }
        if (lane < 20) {
#pragma unroll
            for (int k = 0; k < 10; k++) dzr[k] = dzW1[lane * 10 + k];
            bdz = dzb1[lane];
        }
        if (lane < 30) {
#pragma unroll
            for (int k = 0; k < 10; k++) whh1r[k] = W_hh1[lane * 10 + k];
            bhh1 = b_hh1[lane]; bih1 = b_ih1[lane];
        }
        if (lane < 10) h1p = h1_0[lane];
        __syncthreads();                               // prologue barrier only

        for (int t = 0; t < TT; t++) {
            // --- hdz + gh1 from h1 (shfl broadcast) ---
            float adz = bdz, agh = bhh1;
#pragma unroll
            for (int k = 0; k < 10; k++) {
                float hk = __shfl_sync(0xFFFFFFFFu, h1p, k);
                adz = fmaf(dzr[k], hk, adz);
                agh = fmaf(whh1r[k], hk, agh);
            }
            float hdzo = fmaxf(adz, 0.0f);             // lanes 0..19 valid
            ull hdzv[10];
#pragma unroll
            for (int k = 0; k < 10; k++) {
                float lo = __shfl_sync(0xFFFFFFFFu, hdzo, 2 * k);
                float hi = __shfl_sync(0xFFFFFFFFu, hdzo, 2 * k + 1);
                hdzv[k] = pack2(lo, hi);
            }
            // --- z head (3-4 rows per lane, register weights) ---
            float* o = out + ((size_t)bb * TT + t) * OUTD;
#pragma unroll
            for (int m = 0; m < 4; m++) {
                int row = lane + 32 * m;
                if (m < nr) {
                    float zl = dot_rw<10>(wzl[m], hdzv) + bzl4[m];
                    float zs = softplus_f(dot_rw<10>(wzs[m], hdzv) + bzs4[m]);
                    float zt = fmaf(zs, er4[m], zl);
                    o[200 + row] = zl; o[300 + row] = zs; o[400 + row] = zt;
                    s_z[wid][row] = zt;
                }
            }
            if (t + 1 < TT) {                          // eps prefetch (t+1)
#pragma unroll
                for (int m = 0; m < 4; m++) {
                    int row = lane + 32 * m;
                    if (m < nr && row < 100)
                        er4[m] = eps[((size_t)bb * TT + t + 1) * 100 + row];
                }
            }
            __syncwarp();
            // --- gi1 (shared weights, broadcast z) ---
            float g = 0.f;
            if (lane < 30) {
                const ull* wr = s_wa + lane * 51;
                const ull* zv = (const ull*)&s_z[wid][0];
                g = dot4<50>(wr, zv) + bih1;
            }
            float gA  = __shfl_sync(0xFFFFFFFFu, g,   (lane + 10) & 31);
            float gB  = __shfl_sync(0xFFFFFFFFu, g,   (lane + 20) & 31);
            float ghA = __shfl_sync(0xFFFFFFFFu, agh, (lane + 10) & 31);
            float ghB = __shfl_sync(0xFFFFFFFFu, agh, (lane + 20) & 31);
            float h1n = 0.f;
            if (lane < 10) {
                float r  = sigm(g + agh);
                float uu = sigm(gA + ghA);
                float n  = tanh_f(fmaf(r, ghB, gB));
                h1n = fmaf(uu, h1p - n, n);
                h1p = h1n;
                g_h1buf[((size_t)bb * TT + t) * 10 + lane] = h1n;
            }
            __syncwarp();                              // protect s_z reads
        }
    } else {
        // ================= h2 (RNN2) scan warp =================
        const int rb = wid - 2;
        const int bb = b0 + rb;
        ull wih2r[50];
        float whh2r[10], h2all[10];
        float bih2r = 0.f, bhh2r = 0.f, h2own = 0.f;
#pragma unroll
        for (int q = 0; q < 50; q++) wih2r[q] = 0ull;
#pragma unroll
        for (int k = 0; k < 10; k++) { whh2r[k] = 0.f; h2all[k] = h2_0[k]; }
        if (lane < 30) {
            const float2* p = (const float2*)(W_ih2 + lane * 100);
#pragma unroll
            for (int q = 0; q < 50; q++) { float2 v = p[q]; wih2r[q] = pack2(v.x, v.y); }
#pragma unroll
            for (int k = 0; k < 10; k++) whh2r[k] = W_hh2[lane * 10 + k];
            bih2r = b_ih2[lane]; bhh2r = b_hh2[lane];
        }
        if (lane < 10) h2own = h2_0[lane];
        __syncthreads();                               // prologue barrier only

        float4 pre = make_float4(0.f, 0.f, 0.f, 0.f);
        for (int t = 0; t < TT; t++) {
            // publish h2_shift[t] BEFORE consuming x_t
            if (lane < 10)
                g_h2buf[((size_t)bb * TT + t) * 10 + lane] = h2own;
            if (lane < 25 && t + 2 < TT)               // x(t+2) prefetch
                pre = ((const float4*)(x + ((size_t)bb * TT + t + 2) * 100))[lane];
            // gi2 + gh2 + combine
            float g = 0.f, gh = 0.f;
            if (lane < 30) {
                const ull* xr = (const ull*)&s_x[t % 3][rb][0];
                g = dot4<50>(wih2r, xr) + bih2r;
                gh = bhh2r;
#pragma unroll
                for (int k = 0; k < 10; k++) gh = fmaf(whh2r[k], h2all[k], gh);
            }
            float gA  = __shfl_sync(0xFFFFFFFFu, g,  (lane + 10) & 31);
            float gB  = __shfl_sync(0xFFFFFFFFu, g,  (lane + 20) & 31);
            float ghA = __shfl_sync(0xFFFFFFFFu, gh, (lane + 10) & 31);
            float ghB = __shfl_sync(0xFFFFFFFFu, gh, (lane + 20) & 31);
            float h2n = 0.f;
            if (lane < 10) {
                float r  = sigm(g + gh);
                float uu = sigm(gA + ghA);
                float n  = tanh_f(fmaf(r, ghB, gB));
                h2n = fmaf(uu, h2own - n, n);
                h2own = h2n;
            }
#pragma unroll
            for (int k = 0; k < 10; k++) h2all[k] = __shfl_sync(0xFFFFFFFFu, h2n, k);
            if (lane < 25 && t + 2 < TT)
                ((float4*)&s_x[(t + 2) % 3][rb][0])[lane] = pre;
            __syncwarp();
        }
    }
}

// =====================================================================
// Kernel 2: x-head. 256 blocks (one per batch) x 256 threads.
// =====================================================================
__global__ void __launch_bounds__(256, 2)
xhead_kernel(const float* __restrict__ dxW1, const float* __restrict__ dxb1,
             const float* __restrict__ dxWloc, const float* __restrict__ dxbloc,
             const float* __restrict__ dxWsc, const float* __restrict__ dxbsc,
             float* __restrict__ out) {
    __shared__ __align__(16) float s_cat[16][20];
    __shared__ __align__(16) float s_hdx[16][20];
    __shared__ float s_W1[400], s_b1[20];

    const int tid = threadIdx.x;
    const int b   = blockIdx.x;

    for (int i = tid; i < 400; i += 256) s_W1[i] = dxW1[i];
    if (tid < 20) s_b1[tid] = dxb1[tid];

    // row-thread weights in registers
    ull wx[10];
    float bx = 0.f;
    int j = 0, head = 0;
    if (tid < 200) {
        head = tid / 100; j = tid % 100;
        const float2* p = (const float2*)((head ? dxWsc : dxWloc) + j * 20);
#pragma unroll
        for (int q = 0; q < 10; q++) { float2 v = p[q]; wx[q] = pack2(v.x, v.y); }
        bx = head ? dxbsc[j] : dxbloc[j];
    }
    __syncthreads();

    for (int c = 0; c < 32; c++) {
        const int t0 = c * 16;
        // load cat = [h1n_t, h2shift_t] for 16 timesteps
        for (int i = tid; i < 320; i += 256) {
            int tt = i / 20, k = i % 20;
            s_cat[tt][k] = (k < 10)
                ? g_h1buf[((size_t)b * TT + t0 + tt) * 10 + k]
                : g_h2buf[((size_t)b * TT + t0 + tt) * 10 + (k - 10)];
        }
        __syncthreads();
        // hdx
        for (int i = tid; i < 320; i += 256) {
            int tt = i / 20, jj = i % 20;
            float a = s_b1[jj];
#pragma unroll
            for (int k = 0; k < 20; k++) a = fmaf(s_W1[jj * 20 + k], s_cat[tt][k], a);
            s_hdx[tt][jj] = fmaxf(a, 0.0f);
        }
        __syncthreads();
        // 200 output rows x 16 timesteps
        if (tid < 200) {
#pragma unroll 4
            for (int tt = 0; tt < 16; tt++) {
                float v = dot_rw<10>(wx, (const ull*)&s_hdx[tt][0]) + bx;
                if (head) v = softplus_f(v);
                out[((size_t)b * TT + t0 + tt) * OUTD + head * 100 + j] = v;
            }
        }
        __syncthreads();
    }
}

extern "C" void kernel_launch(void* const* d_in, const int* in_sizes, int n_in,
                              void* d_out, int out_size) {
    const float* x      = (const float*)d_in[0];
    const float* eps    = (const float*)d_in[1];
    const float* W_ih1  = (const float*)d_in[2];
    const float* W_hh1  = (const float*)d_in[3];
    const float* b_ih1  = (const float*)d_in[4];
    const float* b_hh1  = (const float*)d_in[5];
    const float* W_ih2  = (const float*)d_in[6];
    const float* W_hh2  = (const float*)d_in[7];
    const float* b_ih2  = (const float*)d_in[8];
    const float* b_hh2  = (const float*)d_in[9];
    const float* dzW1   = (const float*)d_in[10];
    const float* dzb1   = (const float*)d_in[11];
    const float* dzWloc = (const float*)d_in[12];
    const float* dzbloc = (const float*)d_in[13];
    const float* dzWsc  = (const float*)d_in[14];
    const float* dzbsc  = (const float*)d_in[15];
    const float* dxW1   = (const float*)d_in[16];
    const float* dxb1   = (const float*)d_in[17];
    const float* dxWloc = (const float*)d_in[18];
    const float* dxbloc = (const float*)d_in[19];
    const float* dxWsc  = (const float*)d_in[20];
    const float* dxbsc  = (const float*)d_in[21];
    const float* h1_0   = (const float*)d_in[22];
    const float* h2_0   = (const float*)d_in[23];

    scan_kernel<<<128, 128>>>(x, eps, W_ih1, W_hh1, b_ih1, b_hh1,
                              W_ih2, W_hh2, b_ih2, b_hh2,
                              dzW1, dzb1, dzWloc, dzbloc, dzWsc, dzbsc,
                              h1_0, h2_0, (float*)d_out);
    xhead_kernel<<<256, 256>>>(dxW1, dxb1, dxWloc, dxbloc, dxWsc, dxbsc,
                               (float*)d_out);
}